// round 2
// baseline (speedup 1.0000x reference)
#include <cuda_runtime.h>
#include <math.h>

// ----------------------------------------------------------------------------
// RelNet forward:  N=64, C=64, H=W=8 (HW=64), E=256, G=512, FD=512, GIN=388
// pairs(n, i*64+j) = [feat_i(66) | feat_j(66) | ques(256)]
// Layer-1 decomposition: pairs@W1 = feat_i@W1a + feat_j@W1b + ques@W1c
// ----------------------------------------------------------------------------

#define NB   64
#define HW   64
#define FDIM 66
#define G    512
#define E    256
#define MROWS (NB * HW * HW)   // 262144

// Scratch (device globals: sanctioned workaround; no allocation in kernel_launch)
__device__ float g_bufA[(size_t)MROWS * G];   // 512 MB
__device__ float g_bufB[(size_t)MROWS * G];   // 512 MB
__device__ float g_Ai [(size_t)NB * HW * G];  // feat_i @ W1a   (4096 x 512)
__device__ float g_Bj [(size_t)NB * HW * G];  // feat_j @ W1b   (4096 x 512)
__device__ float g_Cq [NB * G];               // ques @ W1c + b1
__device__ float g_ctx_part[NB * 8 * G];
__device__ float g_ctx[NB * G];

// ---- packed f32x2 helpers (Blackwell FFMA2: 2x fp32 FMA throughput) --------
__device__ __forceinline__ unsigned long long pack2(float x, float y) {
    unsigned long long r;
    asm("mov.b64 %0, {%1, %2};" : "=l"(r) : "f"(x), "f"(y));
    return r;
}
__device__ __forceinline__ void ffma2(unsigned long long &d,
                                      unsigned long long a,
                                      unsigned long long b) {
    asm("fma.rn.f32x2 %0, %1, %2, %0;" : "+l"(d) : "l"(a), "l"(b));
}
__device__ __forceinline__ float2 unpack2(unsigned long long v) {
    float2 r;
    asm("mov.b64 {%0, %1}, %2;" : "=f"(r.x), "=f"(r.y) : "l"(v));
    return r;
}

// ---- K1: A = feat_i @ W1a, B = feat_j @ W1b  (rows = n*64+p, 4096 total) ---
__global__ void k_ab(const float* __restrict__ img, const float* __restrict__ w1) {
    int row = blockIdx.x;           // 0..4095
    int n = row >> 6, p = row & 63;
    __shared__ float f[FDIM];
    int tid = threadIdx.x;          // 512
    if (tid < 64) f[tid] = img[((size_t)n * 64 + tid) * 64 + p];  // img[n, c, p]
    else if (tid == 64) f[64] = (float)(p >> 3);                  // row coord
    else if (tid == 65) f[65] = (float)(p & 7);                   // col coord
    __syncthreads();
    float a = 0.f, b = 0.f;
    #pragma unroll 6
    for (int c = 0; c < FDIM; ++c) {
        float fv = f[c];
        a = fmaf(fv, w1[(size_t)c * G + tid], a);
        b = fmaf(fv, w1[(size_t)(c + FDIM) * G + tid], b);
    }
    g_Ai[(size_t)row * G + tid] = a;
    g_Bj[(size_t)row * G + tid] = b;
}

// ---- K2: Cq = ques @ W1c + b1 ----------------------------------------------
__global__ void k_cq(const float* __restrict__ ques, const float* __restrict__ w1,
                     const float* __restrict__ b1) {
    int n = blockIdx.x, tid = threadIdx.x;    // 512 threads
    __shared__ float q[E];
    if (tid < E) q[tid] = ques[n * E + tid];
    __syncthreads();
    float s = b1[tid];
    #pragma unroll 8
    for (int e = 0; e < E; ++e)
        s = fmaf(q[e], w1[(size_t)(2 * FDIM + e) * G + tid], s);
    g_Cq[n * G + tid] = s;
}

// ---- K3: h1 = relu(A_i + B_j + Cq)  -> g_bufA ------------------------------
__global__ void k_h1() {
    int row = blockIdx.x;               // 0..262143
    int n = row >> 12;
    int i = (row >> 6) & 63;
    int j = row & 63;
    int k = threadIdx.x;                // 512
    float v = g_Ai[(size_t)(n * 64 + i) * G + k]
            + g_Bj[(size_t)(n * 64 + j) * G + k]
            + g_Cq[n * G + k];
    g_bufA[(size_t)row * G + k] = fmaxf(v, 0.f);
}

// ---- K4: big GEMM  C = relu(A @ W + b),  M x 512 x 512, fp32 FFMA2 ---------
// BM=128, BN=128, BK=16, 256 threads, 8x8 per thread (cols packed in f32x2)
__global__ void k_gemm(int srcSel, const float* __restrict__ W,
                       const float* __restrict__ bias, int dstSel) {
    const float* __restrict__ A = srcSel ? g_bufB : g_bufA;
    float* __restrict__ C       = dstSel ? g_bufB : g_bufA;

    __shared__ __align__(16) float As[16 * 128];   // [k][m]
    __shared__ __align__(16) float Bs[16 * 128];   // [k][n]

    const int tid = threadIdx.x;
    const int tr = tid >> 4;          // 0..15
    const int tc = tid & 15;          // 0..15
    const size_t aBase = (size_t)blockIdx.x * 128 * 512;
    const int    nBase = blockIdx.y * 128;

    unsigned long long acc[8][4];
    #pragma unroll
    for (int i = 0; i < 8; ++i)
        #pragma unroll
        for (int j = 0; j < 4; ++j) acc[i][j] = 0ULL;   // = {0.f, 0.f}

    for (int k0 = 0; k0 < 512; k0 += 16) {
        // A tile: 128 rows x 16 cols  (512 float4 loads over 256 threads)
        #pragma unroll
        for (int t = tid; t < 512; t += 256) {
            int r = t >> 2, kc = (t & 3) << 2;
            float4 v = *(const float4*)&A[aBase + (size_t)r * 512 + k0 + kc];
            As[(kc + 0) * 128 + r] = v.x;
            As[(kc + 1) * 128 + r] = v.y;
            As[(kc + 2) * 128 + r] = v.z;
            As[(kc + 3) * 128 + r] = v.w;
        }
        // W tile: 16 rows x 128 cols
        #pragma unroll
        for (int t = tid; t < 512; t += 256) {
            int kr = t >> 5, nc = (t & 31) << 2;
            *(float4*)&Bs[kr * 128 + nc] =
                *(const float4*)&W[(size_t)(k0 + kr) * 512 + nBase + nc];
        }
        __syncthreads();

        #pragma unroll
        for (int kk = 0; kk < 16; ++kk) {
            const float* asp = &As[kk * 128 + tr * 8];
            const unsigned long long* bsp =
                (const unsigned long long*)&Bs[kk * 128 + tc * 8];
            unsigned long long b2[4], ad[8];
            #pragma unroll
            for (int j = 0; j < 4; ++j) b2[j] = bsp[j];
            #pragma unroll
            for (int i = 0; i < 8; ++i) { float av = asp[i]; ad[i] = pack2(av, av); }
            #pragma unroll
            for (int i = 0; i < 8; ++i)
                #pragma unroll
                for (int j = 0; j < 4; ++j)
                    ffma2(acc[i][j], ad[i], b2[j]);
        }
        __syncthreads();
    }

    // epilogue: + bias, relu, store
    float bv[8];
    #pragma unroll
    for (int j = 0; j < 8; ++j) bv[j] = bias[nBase + tc * 8 + j];
    #pragma unroll
    for (int i = 0; i < 8; ++i) {
        size_t row = (size_t)blockIdx.x * 128 + tr * 8 + i;
        float o[8];
        #pragma unroll
        for (int j = 0; j < 4; ++j) {
            float2 v = unpack2(acc[i][j]);
            o[2 * j]     = fmaxf(v.x + bv[2 * j], 0.f);
            o[2 * j + 1] = fmaxf(v.y + bv[2 * j + 1], 0.f);
        }
        float4* dst = (float4*)&C[row * 512 + nBase + tc * 8];
        dst[0] = make_float4(o[0], o[1], o[2], o[3]);
        dst[1] = make_float4(o[4], o[5], o[6], o[7]);
    }
}

// ---- K5: column-mean over 4096 pairs (deterministic two-stage) -------------
__global__ void k_reduce(int srcSel) {
    const float* __restrict__ h4 = srcSel ? g_bufB : g_bufA;
    int n = blockIdx.x, chunk = blockIdx.y, k = threadIdx.x;   // 64 x 8, 512
    const float* base = h4 + ((size_t)n * 4096 + chunk * 512) * 512 + k;
    float s0 = 0.f, s1 = 0.f, s2 = 0.f, s3 = 0.f;
    #pragma unroll 4
    for (int p = 0; p < 512; p += 4) {
        s0 += base[(size_t)(p + 0) * 512];
        s1 += base[(size_t)(p + 1) * 512];
        s2 += base[(size_t)(p + 2) * 512];
        s3 += base[(size_t)(p + 3) * 512];
    }
    g_ctx_part[(n * 8 + chunk) * G + k] = (s0 + s1) + (s2 + s3);
}
__global__ void k_reduce2() {
    int n = blockIdx.x, k = threadIdx.x;
    float s = 0.f;
    #pragma unroll
    for (int c = 0; c < 8; ++c) s += g_ctx_part[(n * 8 + c) * G + k];
    g_ctx[n * G + k] = s * (1.0f / 4096.0f);
}

// ---- K6: f-MLP + log_softmax (one block per batch element) -----------------
__global__ void k_fmlp(const float* __restrict__ fw1, const float* __restrict__ fb1,
                       const float* __restrict__ fw2, const float* __restrict__ fb2,
                       const float* __restrict__ fw3, const float* __restrict__ fb3,
                       float* __restrict__ out) {
    int n = blockIdx.x, tid = threadIdx.x;   // 512 threads
    __shared__ float x[G], y[G];
    __shared__ float sc[2];
    x[tid] = g_ctx[n * G + tid];
    __syncthreads();
    float s = fb1[tid];
    #pragma unroll 8
    for (int c = 0; c < G; ++c) s = fmaf(x[c], fw1[(size_t)c * G + tid], s);
    y[tid] = fmaxf(s, 0.f);
    __syncthreads();
    s = fb2[tid];
    #pragma unroll 8
    for (int c = 0; c < G; ++c) s = fmaf(y[c], fw2[(size_t)c * G + tid], s);
    x[tid] = fmaxf(s, 0.f);
    __syncthreads();
    if (tid < 2) {
        float t = fb3[tid];
        for (int c = 0; c < G; ++c) t = fmaf(x[c], fw3[c * 2 + tid], t);
        sc[tid] = t;
    }
    __syncthreads();
    if (tid == 0) {
        float m = fmaxf(sc[0], sc[1]);
        float lse = m + logf(expf(sc[0] - m) + expf(sc[1] - m));
        out[n * 2 + 0] = sc[0] - lse;
        out[n * 2 + 1] = sc[1] - lse;
    }
}

// ----------------------------------------------------------------------------
extern "C" void kernel_launch(void* const* d_in, const int* in_sizes, int n_in,
                              void* d_out, int out_size) {
    const float* img  = (const float*)d_in[0];
    const float* ques = (const float*)d_in[1];
    const float* g_w1 = (const float*)d_in[2];
    const float* g_b1 = (const float*)d_in[3];
    const float* g_w2 = (const float*)d_in[4];
    const float* g_b2 = (const float*)d_in[5];
    const float* g_w3 = (const float*)d_in[6];
    const float* g_b3 = (const float*)d_in[7];
    const float* g_w4 = (const float*)d_in[8];
    const float* g_b4 = (const float*)d_in[9];
    const float* f_w1 = (const float*)d_in[10];
    const float* f_b1 = (const float*)d_in[11];
    const float* f_w2 = (const float*)d_in[12];
    const float* f_b2 = (const float*)d_in[13];
    const float* f_w3 = (const float*)d_in[14];
    const float* f_b3 = (const float*)d_in[15];
    float* out = (float*)d_out;

    k_ab<<<NB * HW, 512>>>(img, g_w1);
    k_cq<<<NB, 512>>>(ques, g_w1, g_b1);
    k_h1<<<MROWS, 512>>>();                                   // -> bufA (h1)

    dim3 gg(MROWS / 128, 512 / 128);
    k_gemm<<<gg, 256>>>(0, g_w2, g_b2, 1);                    // h2 -> bufB
    k_gemm<<<gg, 256>>>(1, g_w3, g_b3, 0);                    // h3 -> bufA
    k_gemm<<<gg, 256>>>(0, g_w4, g_b4, 1);                    // h4 -> bufB

    k_reduce<<<dim3(NB, 8), 512>>>(1);
    k_reduce2<<<NB, 512>>>();
    k_fmlp<<<NB, 512>>>(f_w1, f_b1, f_w2, f_b2, f_w3, f_b3, out);
}

// round 4
// speedup vs baseline: 4.2292x; 4.2292x over previous
#include <cuda_runtime.h>
#include <cuda_bf16.h>
#include <math.h>
#include <stdint.h>

// ----------------------------------------------------------------------------
// RelNet forward on tcgen05 (sm_103a), bf16 hi/lo split GEMMs (fp32 accuracy-ish)
// N=64, C=64, H=W=8 (HW=64), E=256, G=512, GIN=388
// tcgen05 asm is arch-SPECIFIC: gate on the sm_103a feature macro so the
// harness's plain compute_103 pass compiles a scalar fallback instead.
// ----------------------------------------------------------------------------

#if defined(__CUDA_ARCH__) && (defined(__CUDA_ARCH_FEAT_SM103_ALL) || \
    defined(__CUDA_ARCH_FEAT_SM100_ALL) || defined(__CUDA_ARCH_FEAT_SM101_ALL))
#define TC_OK 1
#else
#define TC_OK 0
#endif

#define NB   64
#define HW   64
#define FDIM 66
#define G    512
#define E    256
#define MROWS (NB * HW * HW)   // 262144

#define BM 128
#define BN 256
#define BK 64
#define KTILES (G / BK)        // 8
#define THREADS 256

// SMEM layout (dynamic)
#define S_OFF_TMEM 0
#define S_OFF_MBAR 8
#define S_OFF_BIAS 16          // 256 floats -> ends at 1040
#define S_OFF_AHI  2048
#define S_OFF_ALO  (S_OFF_AHI + 16384)
#define S_OFF_BHI  (S_OFF_ALO + 16384)
#define S_OFF_BLO  (S_OFF_BHI + 32768)
#define SMEM_SZ    (S_OFF_BLO + 32768)   // 100352

// idesc: kind::f16, dtype=F32(1<<4), atype=BF16(1<<7), btype=BF16(1<<10),
//        N/8=32 (<<17), M/16=8 (<<24)
#define MMA_IDESC ((1u<<4)|(1u<<7)|(1u<<10)|(32u<<17)|(8u<<24))

// SW128 K-major descriptor (layout=2, version=1, SBO=64, LBO=1)
#define SMEM_DESC_BASE_SW128 \
    ((uint64_t(2)<<61)|(uint64_t(1)<<46)|(uint64_t(64)<<32)|(uint64_t(1)<<16))
#define MAKE_SMEM_DESC(a) (SMEM_DESC_BASE_SW128 | ((uint64_t)((a) >> 4) & 0x3FFF))
#define SWZ(o) ((o) ^ (((o) >> 3) & 0x70))

// ---------------- device scratch ----------------
__device__ unsigned       g_pack1[(size_t)MROWS * G];     // h2 (hi,lo) packed
__device__ unsigned       g_pack2[(size_t)MROWS * G];     // h3 (hi,lo) packed
__device__ float          g_Ai[(size_t)NB * HW * G];
__device__ float          g_Bj[(size_t)NB * HW * G];
__device__ float          g_Cq[NB * G];
__device__ float          g_part[(size_t)(MROWS / BM) * G];  // 2048 x 512
__device__ float          g_ctx[NB * G];
__device__ unsigned short g_w2h[G * G], g_w2l[G * G];
__device__ unsigned short g_w3h[G * G], g_w3l[G * G];
__device__ unsigned short g_w4h[G * G], g_w4l[G * G];

// ---------------- generic helpers ----------------
__device__ __forceinline__ unsigned pack_hilo(float v) {
    __nv_bfloat16 h = __float2bfloat16_rn(v);
    float hf = __bfloat162float(h);
    __nv_bfloat16 l = __float2bfloat16_rn(v - hf);
    return (unsigned)__bfloat16_as_ushort(h) |
           ((unsigned)__bfloat16_as_ushort(l) << 16);
}
__device__ __forceinline__ float unpack_sum(unsigned p) {
    return __bfloat162float(__ushort_as_bfloat16((unsigned short)(p & 0xFFFFu))) +
           __bfloat162float(__ushort_as_bfloat16((unsigned short)(p >> 16)));
}

#if TC_OK
// ---------------- tcgen05 PTX helpers (sm_103a only) ----------------
__device__ __forceinline__ uint32_t smem_u32(const void* p) {
    uint32_t a;
    asm("{ .reg .u64 t; cvta.to.shared.u64 t, %1; cvt.u32.u64 %0, t; }"
        : "=r"(a) : "l"(p));
    return a;
}
__device__ __forceinline__ uint32_t elect_one() {
    uint32_t p;
    asm volatile("{ .reg .pred p; elect.sync _|p, 0xFFFFFFFF; selp.b32 %0,1,0,p; }"
                 : "=r"(p));
    return p;
}
__device__ __forceinline__ void mma_bf16_ss(uint32_t d, uint64_t ad, uint64_t bd,
                                            uint32_t idesc, uint32_t en) {
    asm volatile(
        "{\n\t.reg .pred p;\n\tsetp.ne.u32 p, %4, 0;\n\t"
        "tcgen05.mma.cta_group::1.kind::f16 [%0], %1, %2, %3, {%5,%5,%5,%5}, p;\n\t}"
        :: "r"(d), "l"(ad), "l"(bd), "r"(idesc), "r"(en), "r"(0u) : "memory");
}
#define TC_ALLOC(sp, n)  asm volatile("tcgen05.alloc.cta_group::1.sync.aligned.shared::cta.b32 [%0], %1;" :: "r"(sp), "r"(n) : "memory")
#define TC_RELINQ()      asm volatile("tcgen05.relinquish_alloc_permit.cta_group::1.sync.aligned;")
#define TC_DEALLOC(t, n) asm volatile("tcgen05.dealloc.cta_group::1.sync.aligned.b32 %0, %1;" :: "r"(t), "r"(n))
#define TC_COMMIT(mb)    asm volatile("tcgen05.commit.cta_group::1.mbarrier::arrive::one.shared::cluster.b64 [%0];" :: "r"(mb) : "memory")
#define TC_FENCE_AFTER() asm volatile("tcgen05.fence::after_thread_sync;" ::: "memory")
#define TC_WAIT_LD()     asm volatile("tcgen05.wait::ld.sync.aligned;" ::: "memory")
#define FENCE_ASYNC()    asm volatile("fence.proxy.async.shared::cta;" ::: "memory")
#define MBAR_INIT(mb, c) asm volatile("mbarrier.init.shared.b64 [%0], %1;" :: "r"(mb), "r"(c) : "memory")
#define MBAR_INVAL(mb)   asm volatile("mbarrier.inval.shared.b64 [%0];" :: "r"(mb) : "memory")

__device__ __forceinline__ void mbar_wait(uint32_t mb, uint32_t parity) {
    asm volatile(
        "{\n\t.reg .pred P;\n\t"
        "WL_%=:\n\t"
        "mbarrier.try_wait.parity.acquire.cta.shared::cta.b64 P, [%0], %1, 0x989680;\n\t"
        "@P bra.uni WD_%=;\n\t"
        "bra.uni WL_%=;\n\t"
        "WD_%=:\n\t}"
        :: "r"(mb), "r"(parity) : "memory");
}
#define TC_LD_X32(r, a) \
    asm volatile("tcgen05.ld.sync.aligned.32x32b.x32.b32 " \
        "{%0,%1,%2,%3,%4,%5,%6,%7,%8,%9,%10,%11,%12,%13,%14,%15," \
        "%16,%17,%18,%19,%20,%21,%22,%23,%24,%25,%26,%27,%28,%29,%30,%31}, [%32];" \
        : "=r"((r)[0]),"=r"((r)[1]),"=r"((r)[2]),"=r"((r)[3]), \
          "=r"((r)[4]),"=r"((r)[5]),"=r"((r)[6]),"=r"((r)[7]), \
          "=r"((r)[8]),"=r"((r)[9]),"=r"((r)[10]),"=r"((r)[11]), \
          "=r"((r)[12]),"=r"((r)[13]),"=r"((r)[14]),"=r"((r)[15]), \
          "=r"((r)[16]),"=r"((r)[17]),"=r"((r)[18]),"=r"((r)[19]), \
          "=r"((r)[20]),"=r"((r)[21]),"=r"((r)[22]),"=r"((r)[23]), \
          "=r"((r)[24]),"=r"((r)[25]),"=r"((r)[26]),"=r"((r)[27]), \
          "=r"((r)[28]),"=r"((r)[29]),"=r"((r)[30]),"=r"((r)[31]) \
        : "r"(a))
#endif  // TC_OK

// ---- K1: Ai = feat_i @ W1a, Bj = feat_j @ W1b ------------------------------
__global__ void k_ab(const float* __restrict__ img, const float* __restrict__ w1) {
    int row = blockIdx.x;           // 0..4095
    int n = row >> 6, p = row & 63;
    __shared__ float f[FDIM];
    int tid = threadIdx.x;          // 512
    if (tid < 64) f[tid] = img[((size_t)n * 64 + tid) * 64 + p];
    else if (tid == 64) f[64] = (float)(p >> 3);
    else if (tid == 65) f[65] = (float)(p & 7);
    __syncthreads();
    float a = 0.f, b = 0.f;
    #pragma unroll 6
    for (int c = 0; c < FDIM; ++c) {
        float fv = f[c];
        a = fmaf(fv, w1[(size_t)c * G + tid], a);
        b = fmaf(fv, w1[(size_t)(c + FDIM) * G + tid], b);
    }
    g_Ai[(size_t)row * G + tid] = a;
    g_Bj[(size_t)row * G + tid] = b;
}

// ---- K2: Cq = ques @ W1c + b1 ----------------------------------------------
__global__ void k_cq(const float* __restrict__ ques, const float* __restrict__ w1,
                     const float* __restrict__ b1) {
    int n = blockIdx.x, tid = threadIdx.x;    // 512 threads
    __shared__ float q[E];
    if (tid < E) q[tid] = ques[n * E + tid];
    __syncthreads();
    float s = b1[tid];
    #pragma unroll 8
    for (int e = 0; e < E; ++e)
        s = fmaf(q[e], w1[(size_t)(2 * FDIM + e) * G + tid], s);
    g_Cq[n * G + tid] = s;
}

// ---- weight prep: transpose + bf16 hi/lo split  Wt[n][k] -------------------
__global__ void k_wprep(const float* __restrict__ W,
                        unsigned short* __restrict__ hi,
                        unsigned short* __restrict__ lo) {
    int k = blockIdx.x, n = threadIdx.x;      // 512 x 512
    float v = W[(size_t)k * G + n];
    __nv_bfloat16 h = __float2bfloat16_rn(v);
    float hf = __bfloat162float(h);
    __nv_bfloat16 l = __float2bfloat16_rn(v - hf);
    hi[(size_t)n * G + k] = __bfloat16_as_ushort(h);
    lo[(size_t)n * G + k] = __bfloat16_as_ushort(l);
}

// ---- main tcgen05 GEMM -----------------------------------------------------
// MODE 0: A generated from relu(Ai+Bj+Cq), out packed
// MODE 1: A from packIn, out packed
// MODE 2: A from packIn, out = per-CTA column sums of relu(.) (fused mean)
template<int MODE>
__global__ __launch_bounds__(THREADS, 2)
void k_mma(const unsigned* __restrict__ packIn,
           const unsigned short* __restrict__ wHi,
           const unsigned short* __restrict__ wLo,
           const float* __restrict__ bias,
           unsigned* __restrict__ packOut) {
#if TC_OK
    extern __shared__ char smem[];
    const uint32_t sbase = smem_u32(smem);
    const int tid  = threadIdx.x;
    const int wid  = tid >> 5;
    const int lane = tid & 31;
    const int mBlk = blockIdx.x;              // 0..2047
    const int nBase = blockIdx.y * BN;        // 0 or 256

    const uint32_t S_TMEM = sbase + S_OFF_TMEM;
    const uint32_t S_MBAR = sbase + S_OFF_MBAR;
    float* sBias = (float*)(smem + S_OFF_BIAS);

    if (wid == 0) { TC_ALLOC(S_TMEM, 256); TC_RELINQ(); }
    if (tid == 0) MBAR_INIT(S_MBAR, 1);
    sBias[tid] = bias[nBase + tid];
    __syncthreads();
    uint32_t tmem;
    asm volatile("ld.shared.b32 %0, [%1];" : "=r"(tmem) : "r"(S_TMEM));

    for (int t = 0; t < KTILES; ++t) {
        const int kB = t * BK;
        if (t > 0) mbar_wait(S_MBAR, (t - 1) & 1);

        // ---- A tile: 128 rows x 64 k, split into bf16 hi/lo ----
        #pragma unroll
        for (int it = 0; it < 8; ++it) {
            int idx = tid + it * 256;
            int r = idx >> 4, c4 = idx & 15;           // 16 float4 per row
            size_t gr = (size_t)mBlk * BM + r;
            if (MODE == 0) {
                int n = (int)(gr >> 12), i = ((int)gr >> 6) & 63, j = (int)gr & 63;
                const float4 a4 = *(const float4*)&g_Ai[((size_t)(n * 64 + i)) * G + kB + c4 * 4];
                const float4 b4 = *(const float4*)&g_Bj[((size_t)(n * 64 + j)) * G + kB + c4 * 4];
                const float4 q4 = *(const float4*)&g_Cq[(size_t)n * G + kB + c4 * 4];
                float v0 = fmaxf(a4.x + b4.x + q4.x, 0.f);
                float v1 = fmaxf(a4.y + b4.y + q4.y, 0.f);
                float v2 = fmaxf(a4.z + b4.z + q4.z, 0.f);
                float v3 = fmaxf(a4.w + b4.w + q4.w, 0.f);
                unsigned p0 = pack_hilo(v0), p1 = pack_hilo(v1);
                unsigned p2 = pack_hilo(v2), p3 = pack_hilo(v3);
                unsigned off = SWZ((unsigned)(r * 128 + c4 * 8));
                *(uint2*)(smem + S_OFF_AHI + off) =
                    make_uint2((p0 & 0xFFFFu) | (p1 << 16), (p2 & 0xFFFFu) | (p3 << 16));
                *(uint2*)(smem + S_OFF_ALO + off) =
                    make_uint2((p0 >> 16) | (p1 & 0xFFFF0000u), (p2 >> 16) | (p3 & 0xFFFF0000u));
            } else {
                const uint4 p = *(const uint4*)&packIn[gr * G + kB + c4 * 4];
                unsigned off = SWZ((unsigned)(r * 128 + c4 * 8));
                *(uint2*)(smem + S_OFF_AHI + off) =
                    make_uint2((p.x & 0xFFFFu) | (p.y << 16), (p.z & 0xFFFFu) | (p.w << 16));
                *(uint2*)(smem + S_OFF_ALO + off) =
                    make_uint2((p.x >> 16) | (p.y & 0xFFFF0000u), (p.z >> 16) | (p.w & 0xFFFF0000u));
            }
        }
        // ---- B tiles: 256 rows x 64 k bf16 (hi and lo) ----
        #pragma unroll
        for (int it = 0; it < 8; ++it) {
            int idx = tid + it * 256;
            int r = idx >> 3, f4 = idx & 7;            // 8 uint4 per row
            size_t soff = (size_t)(nBase + r) * G + kB + f4 * 8;
            unsigned off = SWZ((unsigned)(r * 128 + f4 * 16));
            *(uint4*)(smem + S_OFF_BHI + off) = *(const uint4*)&wHi[soff];
            *(uint4*)(smem + S_OFF_BLO + off) = *(const uint4*)&wLo[soff];
        }
        __syncthreads();

        if (wid == 0 && elect_one()) {
            FENCE_ASYNC();
            uint64_t adH = MAKE_SMEM_DESC(sbase + S_OFF_AHI);
            uint64_t adL = MAKE_SMEM_DESC(sbase + S_OFF_ALO);
            uint64_t bdH = MAKE_SMEM_DESC(sbase + S_OFF_BHI);
            uint64_t bdL = MAKE_SMEM_DESC(sbase + S_OFF_BLO);
            #pragma unroll
            for (int s = 0; s < 4; ++s) {
                uint64_t o = (uint64_t)(s * 2);
                mma_bf16_ss(tmem, adH + o, bdH + o, MMA_IDESC, (t | s) ? 1u : 0u);
                mma_bf16_ss(tmem, adH + o, bdL + o, MMA_IDESC, 1u);
                mma_bf16_ss(tmem, adL + o, bdH + o, MMA_IDESC, 1u);
            }
            TC_COMMIT(S_MBAR);
        }
    }

    mbar_wait(S_MBAR, (KTILES - 1) & 1);
    TC_FENCE_AFTER();

    // ---- epilogue ----
    float* sPart = (float*)(smem + S_OFF_AHI);   // [4][256] for MODE 2
    if (wid < 4) {
        int lrow = wid * 32 + lane;
        size_t grow = (size_t)mBlk * BM + lrow;
        #pragma unroll 1
        for (int c = 0; c < 8; ++c) {
            uint32_t regs[32];
            TC_LD_X32(regs, tmem + c * 32);
            TC_WAIT_LD();
            if (MODE < 2) {
                uint4* dst = (uint4*)&packOut[grow * G + nBase + c * 32];
                #pragma unroll
                for (int q = 0; q < 8; ++q) {
                    uint4 o;
                    o.x = pack_hilo(fmaxf(__uint_as_float(regs[q*4+0]) + sBias[c*32+q*4+0], 0.f));
                    o.y = pack_hilo(fmaxf(__uint_as_float(regs[q*4+1]) + sBias[c*32+q*4+1], 0.f));
                    o.z = pack_hilo(fmaxf(__uint_as_float(regs[q*4+2]) + sBias[c*32+q*4+2], 0.f));
                    o.w = pack_hilo(fmaxf(__uint_as_float(regs[q*4+3]) + sBias[c*32+q*4+3], 0.f));
                    dst[q] = o;
                }
            } else {
                #pragma unroll
                for (int j = 0; j < 32; ++j) {
                    float v = fmaxf(__uint_as_float(regs[j]) + sBias[c*32+j], 0.f);
                    #pragma unroll
                    for (int o = 16; o > 0; o >>= 1)
                        v += __shfl_xor_sync(0xFFFFFFFFu, v, o);
                    if (lane == 0) sPart[wid * 256 + c * 32 + j] = v;
                }
            }
        }
    }
    __syncthreads();
    if (MODE == 2) {
        float s = sPart[tid] + sPart[256 + tid] + sPart[512 + tid] + sPart[768 + tid];
        g_part[(size_t)mBlk * G + nBase + tid] = s;
        __syncthreads();
    }
    if (tid == 0) MBAR_INVAL(S_MBAR);
    __syncthreads();
    if (wid == 0) TC_DEALLOC(tmem, 256);
#else
    // -------- scalar fallback (compiled for non-sm_103a passes only; correct
    // but slow — never executed when the sm_103a cubin is present) --------
    const int tid  = threadIdx.x;
    const int mBlk = blockIdx.x;
    const int nBase = blockIdx.y * BN;
    const int col = nBase + tid;                 // one output column per thread
    float colsum = 0.f;
    for (int r = 0; r < BM; ++r) {
        size_t gr = (size_t)mBlk * BM + r;
        float acc = bias[col];
        int n = (int)(gr >> 12), i = ((int)gr >> 6) & 63, j = (int)gr & 63;
        for (int k = 0; k < G; ++k) {
            float a;
            if (MODE == 0) {
                a = fmaxf(g_Ai[((size_t)(n * 64 + i)) * G + k]
                        + g_Bj[((size_t)(n * 64 + j)) * G + k]
                        + g_Cq[(size_t)n * G + k], 0.f);
                a = unpack_sum(pack_hilo(a));
            } else {
                a = unpack_sum(packIn[gr * G + k]);
            }
            float w = __bfloat162float(__ushort_as_bfloat16(wHi[(size_t)col * G + k]))
                    + __bfloat162float(__ushort_as_bfloat16(wLo[(size_t)col * G + k]));
            acc = fmaf(a, w, acc);
        }
        float v = fmaxf(acc, 0.f);
        if (MODE < 2) packOut[gr * G + col] = pack_hilo(v);
        else          colsum += v;
    }
    if (MODE == 2) g_part[(size_t)mBlk * G + col] = colsum;
#endif
}

// ---- final mean over 4096 pairs (32 partial blocks per image) --------------
__global__ void k_reduce2() {
    int n = blockIdx.x, k = threadIdx.x;   // 64 x 512
    float s = 0.f;
    #pragma unroll
    for (int b = 0; b < 32; ++b)
        s += g_part[(size_t)(n * 32 + b) * G + k];
    g_ctx[n * G + k] = s * (1.0f / 4096.0f);
}

// ---- f-MLP + log_softmax ---------------------------------------------------
__global__ void k_fmlp(const float* __restrict__ fw1, const float* __restrict__ fb1,
                       const float* __restrict__ fw2, const float* __restrict__ fb2,
                       const float* __restrict__ fw3, const float* __restrict__ fb3,
                       float* __restrict__ out) {
    int n = blockIdx.x, tid = threadIdx.x;   // 512 threads
    __shared__ float x[G], y[G];
    __shared__ float sc[2];
    x[tid] = g_ctx[n * G + tid];
    __syncthreads();
    float s = fb1[tid];
    #pragma unroll 8
    for (int c = 0; c < G; ++c) s = fmaf(x[c], fw1[(size_t)c * G + tid], s);
    y[tid] = fmaxf(s, 0.f);
    __syncthreads();
    s = fb2[tid];
    #pragma unroll 8
    for (int c = 0; c < G; ++c) s = fmaf(y[c], fw2[(size_t)c * G + tid], s);
    x[tid] = fmaxf(s, 0.f);
    __syncthreads();
    if (tid < 2) {
        float t = fb3[tid];
        for (int c = 0; c < G; ++c) t = fmaf(x[c], fw3[c * 2 + tid], t);
        sc[tid] = t;
    }
    __syncthreads();
    if (tid == 0) {
        float m = fmaxf(sc[0], sc[1]);
        float lse = m + logf(expf(sc[0] - m) + expf(sc[1] - m));
        out[n * 2 + 0] = sc[0] - lse;
        out[n * 2 + 1] = sc[1] - lse;
    }
}

// ----------------------------------------------------------------------------
extern "C" void kernel_launch(void* const* d_in, const int* in_sizes, int n_in,
                              void* d_out, int out_size) {
    const float* img  = (const float*)d_in[0];
    const float* ques = (const float*)d_in[1];
    const float* g_w1 = (const float*)d_in[2];
    const float* g_b1 = (const float*)d_in[3];
    const float* g_w2 = (const float*)d_in[4];
    const float* g_b2 = (const float*)d_in[5];
    const float* g_w3 = (const float*)d_in[6];
    const float* g_b3 = (const float*)d_in[7];
    const float* g_w4 = (const float*)d_in[8];
    const float* g_b4 = (const float*)d_in[9];
    const float* f_w1 = (const float*)d_in[10];
    const float* f_b1 = (const float*)d_in[11];
    const float* f_w2 = (const float*)d_in[12];
    const float* f_b2 = (const float*)d_in[13];
    const float* f_w3 = (const float*)d_in[14];
    const float* f_b3 = (const float*)d_in[15];
    float* out = (float*)d_out;

    cudaFuncSetAttribute(k_mma<0>, cudaFuncAttributeMaxDynamicSharedMemorySize, SMEM_SZ);
    cudaFuncSetAttribute(k_mma<1>, cudaFuncAttributeMaxDynamicSharedMemorySize, SMEM_SZ);
    cudaFuncSetAttribute(k_mma<2>, cudaFuncAttributeMaxDynamicSharedMemorySize, SMEM_SZ);

    unsigned short *w2h, *w2l, *w3h, *w3l, *w4h, *w4l;
    unsigned *p1, *p2;
    cudaGetSymbolAddress((void**)&w2h, g_w2h); cudaGetSymbolAddress((void**)&w2l, g_w2l);
    cudaGetSymbolAddress((void**)&w3h, g_w3h); cudaGetSymbolAddress((void**)&w3l, g_w3l);
    cudaGetSymbolAddress((void**)&w4h, g_w4h); cudaGetSymbolAddress((void**)&w4l, g_w4l);
    cudaGetSymbolAddress((void**)&p1, g_pack1); cudaGetSymbolAddress((void**)&p2, g_pack2);

    k_wprep<<<G, G>>>(g_w2, w2h, w2l);
    k_wprep<<<G, G>>>(g_w3, w3h, w3l);
    k_wprep<<<G, G>>>(g_w4, w4h, w4l);
    k_ab<<<NB * HW, 512>>>(img, g_w1);
    k_cq<<<NB, 512>>>(ques, g_w1, g_b1);

    dim3 gg(MROWS / BM, G / BN);   // 2048 x 2
    k_mma<0><<<gg, THREADS, SMEM_SZ>>>(nullptr, w2h, w2l, g_b2, p1);  // h2
    k_mma<1><<<gg, THREADS, SMEM_SZ>>>(p1,      w3h, w3l, g_b3, p2);  // h3
    k_mma<2><<<gg, THREADS, SMEM_SZ>>>(p2,      w4h, w4l, g_b4, nullptr); // sums

    k_reduce2<<<NB, 512>>>();
    k_fmlp<<<NB, 512>>>(f_w1, f_b1, f_w2, f_b2, f_w3, f_b3, out);
}